// round 2
// baseline (speedup 1.0000x reference)
#include <cuda_runtime.h>

// SLSTM (== plain LSTM, reset='none') recurrence + final Linear(128->1).
// B=1024, T=2048, IN=16, H=128, OUT=1.
//
// Persistent kernel: 128 CTAs x 256 threads; CTA owns 8 batch rows for all T.
// Thread (j = tid&127, bh = tid>>7) computes gates i,f,g,o of hidden unit j
// for 4 batch rows (b = 4*bh .. 4*bh+3). K dimension (144 = 128 h + 16 x)
// processed as f32x2 pairs: acc lanes hold even-k / odd-k partial sums.
// Weights: first 36 k's pre-packed in registers, remaining 108 k's in SMEM.
// h/x state double-buffered in SMEM; c state in registers; 1 barrier/step.

#define T_    2048
#define IN_   16
#define H_    128
#define KREG  36          // k's whose weights live in registers (18 pairs)
#define KPREG 18
#define KPSM  54          // 108 k's in smem (54 pairs)
#define BB    8           // batch rows per CTA
#define NT    256
#define NCTA  128
#define HXROW 144         // 128 h + 16 x per (buffer, b)
#define HXBUF (BB * HXROW)

#define WSM_FLOATS (KPSM * 128 * 4 * 2)            // 55296
#define SMEM_FLOATS (WSM_FLOATS + 2 * HXBUF + 128) // 57728
#define SMEM_BYTES  (SMEM_FLOATS * 4)              // 230912

typedef unsigned long long u64;

__device__ __forceinline__ void ffma2(u64 &d, u64 a, u64 b) {
    asm("fma.rn.f32x2 %0, %1, %2, %0;" : "+l"(d) : "l"(a), "l"(b));
}
__device__ __forceinline__ float2 unpk(u64 v) {
    float2 r;
    asm("mov.b64 {%0, %1}, %2;" : "=f"(r.x), "=f"(r.y) : "l"(v));
    return r;
}
__device__ __forceinline__ float ex2a(float x) {
    float y; asm("ex2.approx.f32 %0, %1;" : "=f"(y) : "f"(x)); return y;
}
__device__ __forceinline__ float rcpa(float x) {
    float y; asm("rcp.approx.f32 %0, %1;" : "=f"(y) : "f"(x)); return y;
}
__device__ __forceinline__ float sig_(float x) {
    // 1 / (1 + 2^(-x * log2 e))
    return rcpa(1.0f + ex2a(-1.4426950408889634f * x));
}
__device__ __forceinline__ float tanh_(float x) {
    // 2*sigmoid(2x) - 1
    return 2.0f * rcpa(1.0f + ex2a(-2.8853900817779268f * x)) - 1.0f;
}

extern "C" __global__ void __launch_bounds__(NT, 1)
slstm_kernel(const float* __restrict__ x, const float* __restrict__ W_ih,
             const float* __restrict__ W_hh, const float* __restrict__ b_ih,
             const float* __restrict__ b_hh, const float* __restrict__ fc_w,
             const float* __restrict__ fc_b, float* __restrict__ out)
{
    extern __shared__ float sm[];
    float* Wsm = sm;                        // [kp][j][g] as float pairs
    float* hx  = sm + WSM_FLOATS;           // 2 buffers x [b][144]
    float* fcw = sm + WSM_FLOATS + 2 * HXBUF;

    const int tid = threadIdx.x;
    const int j   = tid & 127;
    const int bh  = tid >> 7;               // 0 or 1
    const int b0  = bh * 4;
    const int bbase = blockIdx.x * BB;

    // ---------- prologue: SMEM weights (k = KREG..143), layout u64[kp*512 + j*4 + g] ----------
    for (int s = tid; s < KPSM * 128 * 4; s += NT) {
        const int g  = s & 3;
        const int jj = (s >> 2) & 127;
        const int kp = s >> 9;
        const int row = g * 128 + jj;
        const int k = KREG + 2 * kp;
        float w0, w1;
        if (k < 128) {
            w0 = W_hh[row * 128 + k];
            w1 = W_hh[row * 128 + k + 1];
        } else {
            w0 = W_ih[row * 16 + (k - 128)];
            w1 = W_ih[row * 16 + (k - 128) + 1];
        }
        Wsm[2 * s]     = w0;
        Wsm[2 * s + 1] = w1;
    }
    if (tid < 128) fcw[tid] = fc_w[tid];

    // ---------- register weights: pairs for k = 0..KREG-1 ----------
    u64 wr[4][KPREG];
#pragma unroll
    for (int g = 0; g < 4; ++g)
#pragma unroll
        for (int kp = 0; kp < KPREG; ++kp)
            wr[g][kp] = *(const u64*)&W_hh[(g * 128 + j) * 128 + 2 * kp];

    float bg[4];
#pragma unroll
    for (int g = 0; g < 4; ++g) bg[g] = b_ih[g * 128 + j] + b_hh[g * 128 + j];

    // ---------- init state: h0 = 0 in buffer 0; x(0) staged ----------
    for (int s = tid; s < BB * 128; s += NT) {
        const int b = s >> 7, k = s & 127;
        hx[b * HXROW + k] = 0.0f;
    }
    if (tid < 128) {
        const int b = tid >> 4, i = tid & 15;
        hx[b * HXROW + 128 + i] = x[(bbase + b) * (T_ * IN_) + i];
    }
    float c[4] = {0.0f, 0.0f, 0.0f, 0.0f};
    __syncthreads();

    const int xb = tid >> 4, xi = tid & 15;

    int cur = 0;
    for (int t = 0; t < T_; ++t) {
        const int nxt = cur ^ 1;

        // prefetch x(t+1) while doing this step's FMAs
        float xv = 0.0f;
        const bool doX = (tid < 128) && (t + 1 < T_);
        if (doX)
            xv = x[(bbase + xb) * (T_ * IN_) + (t + 1) * IN_ + xi];

        const float* hb = hx + cur * HXBUF;

        u64 acc[4][4];
#pragma unroll
        for (int g = 0; g < 4; ++g)
#pragma unroll
            for (int p = 0; p < 4; ++p) acc[g][p] = 0ull;

        // -------- register-weight section (k = 0..35) --------
#pragma unroll
        for (int kp = 0; kp < KPREG; ++kp) {
#pragma unroll
            for (int p = 0; p < 4; ++p) {
                const u64 hp = *(const u64*)&hb[(b0 + p) * HXROW + 2 * kp];
                ffma2(acc[0][p], wr[0][kp], hp);
                ffma2(acc[1][p], wr[1][kp], hp);
                ffma2(acc[2][p], wr[2][kp], hp);
                ffma2(acc[3][p], wr[3][kp], hp);
            }
        }

        // -------- smem-weight section (k = 36..143) --------
        const u64* Wu = (const u64*)Wsm;
#pragma unroll 6
        for (int kp = 0; kp < KPSM; ++kp) {
            const u64* wp = Wu + ((kp * 128 + j) << 2);
            const ulonglong2 wa = *(const ulonglong2*)(wp);       // gates 0,1
            const ulonglong2 wb = *(const ulonglong2*)(wp + 2);   // gates 2,3
#pragma unroll
            for (int p = 0; p < 4; ++p) {
                const u64 hp = *(const u64*)&hb[(b0 + p) * HXROW + KREG + 2 * kp];
                ffma2(acc[0][p], wa.x, hp);
                ffma2(acc[1][p], wa.y, hp);
                ffma2(acc[2][p], wb.x, hp);
                ffma2(acc[3][p], wb.y, hp);
            }
        }

        // -------- activations + state update --------
        float hv[4];
#pragma unroll
        for (int p = 0; p < 4; ++p) {
            const float2 gi = unpk(acc[0][p]);
            const float2 gf = unpk(acc[1][p]);
            const float2 gg = unpk(acc[2][p]);
            const float2 go = unpk(acc[3][p]);
            const float ig = gi.x + gi.y + bg[0];
            const float fg = gf.x + gf.y + bg[1];
            const float gw = gg.x + gg.y + bg[2];
            const float og = go.x + go.y + bg[3];
            const float cn = sig_(fg) * c[p] + sig_(ig) * tanh_(gw);
            c[p] = cn;
            hv[p] = sig_(og) * tanh_(cn);
        }

        float* hn = hx + nxt * HXBUF;
#pragma unroll
        for (int p = 0; p < 4; ++p)
            hn[(b0 + p) * HXROW + j] = hv[p];
        if (doX)
            hn[xb * HXROW + 128 + xi] = xv;

        __syncthreads();
        cur = nxt;
    }

    // ---------- output: out[b] = h_T[b] . fc_w + fc_b ----------
    if (tid < BB) {
        const float* hb = hx + cur * HXBUF + tid * HXROW;
        float s = fc_b[0];
#pragma unroll 8
        for (int k = 0; k < 128; ++k) s += hb[k] * fcw[k];
        out[bbase + tid] = s;
    }
}

extern "C" void kernel_launch(void* const* d_in, const int* in_sizes, int n_in,
                              void* d_out, int out_size)
{
    const float* x    = (const float*)d_in[0];
    const float* W_ih = (const float*)d_in[1];
    const float* W_hh = (const float*)d_in[2];
    const float* b_ih = (const float*)d_in[3];
    const float* b_hh = (const float*)d_in[4];
    const float* fc_w = (const float*)d_in[5];
    const float* fc_b = (const float*)d_in[6];
    float* out = (float*)d_out;

    cudaFuncSetAttribute(slstm_kernel,
                         cudaFuncAttributeMaxDynamicSharedMemorySize, SMEM_BYTES);
    slstm_kernel<<<NCTA, NT, SMEM_BYTES>>>(x, W_ih, W_hh, b_ih, b_hh,
                                           fc_w, fc_b, out);
}

// round 4
// speedup vs baseline: 1.8792x; 1.8792x over previous
#include <cuda_runtime.h>

// LSTM recurrence (SLSTM reset='none') + Linear(128->1).
// B=1024, T=2048, IN=16, H=128.
//
// Persistent: 128 CTAs x 512 threads. CTA owns 8 batch rows for all T.
// Thread (j = (tid>>2)&127, kh = (tid>>1)&1, g2 = tid&1):
//   computes gate-pair {2*g2, 2*g2+1} of hidden unit j, for all 8 batch rows,
//   over K-half kh (72 of 144 k's). f32x2 packed FMAs (k-pairs in lanes).
// Weights: 40 k's in registers (20 per kh-half), 104 k's in SMEM, each SMEM
// weight read by exactly ONE thread per step (no duplication).
// Partial sums combined with shfl.xor(2) (kh halves); gate halves exchanged
// with shfl.xor(1). One __syncthreads per step. c state in registers of
// g2==0 threads (4 batch rows each, split by kh).

#define T_    2048
#define IN_   16
#define KREG  40            // k's in registers (20 per kh half, 5 float4 chunks)
#define NT    512
#define NCTA  128
#define BB    8
#define HXROW 144
#define HXBUF (BB * HXROW)          // 1152 floats
#define WSM_U64 (26 * 1024)         // 26624 u64 = 104 k x 512 gate-rows
#define WSM_FLOATS (WSM_U64 * 2)    // 53248
#define SMEM_FLOATS (WSM_FLOATS + 2 * HXBUF + 128)   // 55680
#define SMEM_BYTES  (SMEM_FLOATS * 4)                // 222720

typedef unsigned long long u64;

__device__ __forceinline__ void ffma2(u64 &d, u64 a, u64 b) {
    asm("fma.rn.f32x2 %0, %1, %2, %0;" : "+l"(d) : "l"(a), "l"(b));
}
__device__ __forceinline__ float2 unpk(u64 v) {
    float2 r;
    asm("mov.b64 {%0, %1}, %2;" : "=f"(r.x), "=f"(r.y) : "l"(v));
    return r;
}
__device__ __forceinline__ float ex2a(float x) {
    float y; asm("ex2.approx.f32 %0, %1;" : "=f"(y) : "f"(x)); return y;
}
__device__ __forceinline__ float rcpa(float x) {
    float y; asm("rcp.approx.f32 %0, %1;" : "=f"(y) : "f"(x)); return y;
}
__device__ __forceinline__ float sig_(float x) {
    return rcpa(1.0f + ex2a(-1.4426950408889634f * x));
}
__device__ __forceinline__ float tanh_(float x) {
    return 2.0f * rcpa(1.0f + ex2a(-2.8853900817779268f * x)) - 1.0f;
}

extern "C" __global__ void __launch_bounds__(NT, 1)
slstm_kernel(const float* __restrict__ x, const float* __restrict__ W_ih,
             const float* __restrict__ W_hh, const float* __restrict__ b_ih,
             const float* __restrict__ b_hh, const float* __restrict__ fc_w,
             const float* __restrict__ fc_b, float* __restrict__ out)
{
    extern __shared__ float sm[];
    float* Wsm = sm;                          // 104 k x 512 rows, packed pairs
    float* hx  = sm + WSM_FLOATS;             // 2 x [8][144]
    float* fcw = sm + WSM_FLOATS + 2 * HXBUF;

    const int tid = threadIdx.x;
    const int g2  = tid & 1;                  // 0: gates i,f   1: gates g,o
    const int kh  = (tid >> 1) & 1;           // K half
    const int j   = (tid >> 2) & 127;         // hidden unit
    const int bbase = blockIdx.x * BB;

    // ---- prologue: SMEM weights for k = KREG..143 ----
    // u64 index = kp_local*1024 + j*8 + kh*4 + g2*2 + gg
    //   kp_local in [0,26) : k-pair within this kh's 52 k's
    //   k0 = KREG + kh*52 + 2*kp_local
    for (int s = tid; s < WSM_U64; s += NT) {
        const int gg  = s & 1;
        const int gs2 = (s >> 1) & 1;
        const int khs = (s >> 2) & 1;
        const int jj  = (s >> 3) & 127;
        const int kp  = s >> 10;              // 0..25
        const int g   = 2 * gs2 + gg;
        const int k0  = KREG + khs * 52 + 2 * kp;
        const int row = g * 128 + jj;
        float w0, w1;
        if (k0 < 128) {
            w0 = W_hh[row * 128 + k0];
            w1 = W_hh[row * 128 + k0 + 1];
        } else {
            w0 = W_ih[row * 16 + (k0 - 128)];
            w1 = W_ih[row * 16 + (k0 - 127)];
        }
        Wsm[2 * s]     = w0;
        Wsm[2 * s + 1] = w1;
    }
    if (tid < 128) fcw[tid] = fc_w[tid];

    // ---- register weights: k = kh*20 .. kh*20+19 (10 pairs x 2 gates) ----
    u64 wr[2][10];
#pragma unroll
    for (int gg = 0; gg < 2; ++gg) {
        const int row = (2 * g2 + gg) * 128 + j;
#pragma unroll
        for (int i = 0; i < 10; ++i)
            wr[gg][i] = *(const u64*)&W_hh[row * 128 + kh * 20 + 2 * i];
    }

    const float bg0 = b_ih[(2 * g2)     * 128 + j] + b_hh[(2 * g2)     * 128 + j];
    const float bg1 = b_ih[(2 * g2 + 1) * 128 + j] + b_hh[(2 * g2 + 1) * 128 + j];

    // ---- init: h0 = 0, x(0) staged ----
    for (int s = tid; s < BB * 128; s += NT) {
        const int b = s >> 7, k = s & 127;
        hx[b * HXROW + k] = 0.0f;
    }
    if (tid < 128) {
        const int b = tid >> 4, i = tid & 15;
        hx[b * HXROW + 128 + i] = x[(bbase + b) * (T_ * IN_) + i];
    }
    float c[4] = {0.0f, 0.0f, 0.0f, 0.0f};   // batch rows kh*4 .. kh*4+3 (g2==0)
    __syncthreads();

    const int khr = kh * 20;          // reg-section h float offset
    const int khs = KREG + kh * 52;   // smem-section h float offset
    const u64* Wu = (const u64*)Wsm;
    const int wb  = j * 8 + kh * 4 + g2 * 2;   // this thread's weight base (u64)

    int cur = 0;
    for (int t = 0; t < T_; ++t) {
        // prefetch x(t+1)
        float xv = 0.0f;
        const bool doX = (tid < 128) && (t + 1 < T_);
        if (doX)
            xv = x[(bbase + (tid >> 4)) * (T_ * IN_) + (t + 1) * IN_ + (tid & 15)];

        const float* hb = hx + cur * HXBUF;

        u64 acc0[8], acc1[8];
#pragma unroll
        for (int p = 0; p < 8; ++p) { acc0[p] = 0ull; acc1[p] = 0ull; }

        // -------- register-weight section: 5 float4 chunks --------
#pragma unroll
        for (int cc = 0; cc < 5; ++cc) {
            const u64 wa0 = wr[0][2 * cc],     wa1 = wr[1][2 * cc];
            const u64 wb0 = wr[0][2 * cc + 1], wb1 = wr[1][2 * cc + 1];
#pragma unroll
            for (int p = 0; p < 8; ++p) {
                const ulonglong2 hv =
                    *(const ulonglong2*)&hb[p * HXROW + khr + 4 * cc];
                ffma2(acc0[p], wa0, hv.x);
                ffma2(acc1[p], wa1, hv.x);
                ffma2(acc0[p], wb0, hv.y);
                ffma2(acc1[p], wb1, hv.y);
            }
        }

        // -------- smem-weight section: 13 float4 chunks --------
#pragma unroll
        for (int cc = 0; cc < 13; ++cc) {
            const ulonglong2 wA = *(const ulonglong2*)(Wu + wb + (2 * cc)     * 1024);
            const ulonglong2 wB = *(const ulonglong2*)(Wu + wb + (2 * cc + 1) * 1024);
#pragma unroll
            for (int p = 0; p < 8; ++p) {
                const ulonglong2 hv =
                    *(const ulonglong2*)&hb[p * HXROW + khs + 4 * cc];
                ffma2(acc0[p], wA.x, hv.x);
                ffma2(acc1[p], wA.y, hv.x);
                ffma2(acc0[p], wB.x, hv.y);
                ffma2(acc1[p], wB.y, hv.y);
            }
        }

        // -------- reduce: lane-sum + kh-partner + bias --------
        float s0[8], s1[8];
#pragma unroll
        for (int p = 0; p < 8; ++p) {
            const float2 a = unpk(acc0[p]);
            float v = a.x + a.y;
            v += __shfl_xor_sync(0xffffffffu, v, 2);
            s0[p] = v + bg0;
            const float2 b = unpk(acc1[p]);
            float w = b.x + b.y;
            w += __shfl_xor_sync(0xffffffffu, w, 2);
            s1[p] = w + bg1;
        }

        // -------- activations: this thread handles p = kh*4 .. kh*4+3 --------
        float* hn = hx + (cur ^ 1) * HXBUF;
#pragma unroll
        for (int pp = 0; pp < 4; ++pp) {
            const int p = kh * 4 + pp;
            // A (g2==0): va=sig(i), vb=sig(f).  B (g2==1): va=tanh(g), vb=sig(o)
            float va, vb;
            if (g2 == 0) { va = sig_(s0[p]);  vb = sig_(s1[p]); }
            else         { va = tanh_(s0[p]); vb = sig_(s1[p]); }
            // exchange: A <- tanh(g), B <- sig(i) (unused)
            const float r1 = __shfl_xor_sync(0xffffffffu, va, 1);
            // A: c_new = sig(f)*c + sig(i)*tanh(g)   (finite garbage on B)
            const float cn = vb * c[pp] + va * r1;
            const float tc = tanh_(cn);
            // A sends tanh(c_new), B sends sig(o); A receives sig(o)
            const float r2 = __shfl_xor_sync(0xffffffffu, g2 ? vb : tc, 1);
            if (g2 == 0) {
                c[pp] = cn;
                hn[p * HXROW + j] = r2 * tc;   // sig(o) * tanh(c_new)
            }
        }
        if (doX)
            hn[(tid >> 4) * HXROW + 128 + (tid & 15)] = xv;

        __syncthreads();
        cur ^= 1;
    }

    // ---- output: out[b] = h_T[b] . fc_w + fc_b ----
    if (tid < BB) {
        const float* hbf = hx + cur * HXBUF + tid * HXROW;
        float s = fc_b[0];
#pragma unroll 8
        for (int k = 0; k < 128; ++k) s += hbf[k] * fcw[k];
        out[bbase + tid] = s;
    }
}

extern "C" void kernel_launch(void* const* d_in, const int* in_sizes, int n_in,
                              void* d_out, int out_size)
{
    const float* x    = (const float*)d_in[0];
    const float* W_ih = (const float*)d_in[1];
    const float* W_hh = (const float*)d_in[2];
    const float* b_ih = (const float*)d_in[3];
    const float* b_hh = (const float*)d_in[4];
    const float* fc_w = (const float*)d_in[5];
    const float* fc_b = (const float*)d_in[6];
    float* out = (float*)d_out;

    cudaFuncSetAttribute(slstm_kernel,
                         cudaFuncAttributeMaxDynamicSharedMemorySize, SMEM_BYTES);
    slstm_kernel<<<NCTA, NT, SMEM_BYTES>>>(x, W_ih, W_hh, b_ih, b_hh,
                                           fc_w, fc_b, out);
}